// round 2
// baseline (speedup 1.0000x reference)
#include <cuda_runtime.h>

// Problem-fixed shapes
#define NN 262144
#define EE 4194304
#define BN_EPS 1e-5f

// ---------------- scratch (static device globals; no allocation) ----------------
__device__ float  d_deg[NN];
__device__ float  d_dinv[NN];
__device__ float  d_agg1[NN];
__device__ float  d_h3pre[NN];
__device__ float  d_agg3[NN];
__device__ float4 d_h2pre[NN];
__device__ float4 d_agg2[NN];
__device__ float  d_norm[EE];   // per-edge symmetric norm (shared by all 3 layers)

// folded per-layer affine params
__device__ float d_a1[16], d_c1[16];   // layer1: relu(agg1*a1 + c1)
__device__ float d_W2v[64];            // [16,4] row-major
__device__ float d_s2[4], d_c2[4];     // layer2 bn fold
__device__ float d_W3v[4];
__device__ float d_za, d_zc;           // final: sigmoid(agg3*za + zc)

// ---------------- kernels ----------------

__global__ void k_params(const float* __restrict__ W1, const float* __restrict__ b1,
                         const float* __restrict__ W2, const float* __restrict__ b2,
                         const float* __restrict__ W3, const float* __restrict__ b3,
                         const float* __restrict__ g1, const float* __restrict__ be1,
                         const float* __restrict__ m1, const float* __restrict__ v1,
                         const float* __restrict__ g2, const float* __restrict__ be2,
                         const float* __restrict__ m2, const float* __restrict__ v2,
                         const float* __restrict__ We, const float* __restrict__ bee) {
    int t = threadIdx.x;
    if (t < 16) {
        float s = g1[t] * rsqrtf(v1[t] + BN_EPS);
        d_a1[t] = W1[t] * s;                       // W1 is [1,16]
        d_c1[t] = (b1[t] - m1[t]) * s + be1[t];
    }
    if (t < 64) d_W2v[t] = W2[t];
    if (t < 4) {
        float s = g2[t] * rsqrtf(v2[t] + BN_EPS);
        d_s2[t] = s;
        d_c2[t] = (b2[t] - m2[t]) * s + be2[t];
        d_W3v[t] = W3[t];
    }
    if (t == 0) { d_za = We[0]; d_zc = b3[0] * We[0] + bee[0]; }
}

__global__ void k_initdeg() {
    int i = blockIdx.x * blockDim.x + threadIdx.x;
    if (i < NN) d_deg[i] = 1.0f;   // self-loop weight
}

// degree accumulation (edge_index is int32 [2, E]: row 0 = src, row 1 = dst)
__global__ void k_deg(const int* __restrict__ ei, const float* __restrict__ ew) {
    int e = blockIdx.x * blockDim.x + threadIdx.x;
    if (e < EE) {
        int d = ei[EE + e];
        atomicAdd(&d_deg[d], ew[e]);
    }
}

// dinv + layer-1 self-loop init: agg1[i] = dinv^2 * x[i]
__global__ void k_dinv(const float* __restrict__ x) {
    int i = blockIdx.x * blockDim.x + threadIdx.x;
    if (i < NN) {
        float di = rsqrtf(d_deg[i]);
        d_dinv[i] = di;
        d_agg1[i] = x[i] * di * di;
    }
}

// edge pass 1: compute+store norm, scalar gather/scatter of x
__global__ void k_e1(const int* __restrict__ ei, const float* __restrict__ ew,
                     const float* __restrict__ x) {
    int e = blockIdx.x * blockDim.x + threadIdx.x;
    if (e < EE) {
        int s = ei[e];
        int d = ei[EE + e];
        float nm = d_dinv[s] * ew[e] * d_dinv[d];
        d_norm[e] = nm;
        atomicAdd(&d_agg1[d], nm * __ldg(&x[s]));
    }
}

// node pass 1: bias+bn+relu (folded) -> W2 -> h2pre; init agg2 with self loop
__global__ void k_n1() {
    int i = blockIdx.x * blockDim.x + threadIdx.x;
    if (i < NN) {
        float t = d_agg1[i];
        float a0 = 0.f, a1 = 0.f, a2 = 0.f, a3 = 0.f;
#pragma unroll
        for (int j = 0; j < 16; j++) {
            float p = fmaxf(fmaf(t, d_a1[j], d_c1[j]), 0.f);
            a0 = fmaf(p, d_W2v[j * 4 + 0], a0);
            a1 = fmaf(p, d_W2v[j * 4 + 1], a1);
            a2 = fmaf(p, d_W2v[j * 4 + 2], a2);
            a3 = fmaf(p, d_W2v[j * 4 + 3], a3);
        }
        float4 h = make_float4(a0, a1, a2, a3);
        d_h2pre[i] = h;
        float di = d_dinv[i];
        float r = di * di;
        d_agg2[i] = make_float4(h.x * r, h.y * r, h.z * r, h.w * r);
    }
}

// edge pass 2: 4-wide gather/scatter
__global__ void k_e2(const int* __restrict__ ei) {
    int e = blockIdx.x * blockDim.x + threadIdx.x;
    if (e < EE) {
        int s = ei[e];
        int d = ei[EE + e];
        float nm = d_norm[e];
        float4 h = d_h2pre[s];
        float* base = (float*)&d_agg2[d];
        atomicAdd(base + 0, nm * h.x);
        atomicAdd(base + 1, nm * h.y);
        atomicAdd(base + 2, nm * h.z);
        atomicAdd(base + 3, nm * h.w);
    }
}

// node pass 2: bias+bn+relu (folded) -> W3 -> h3pre; init agg3 with self loop
__global__ void k_n2() {
    int i = blockIdx.x * blockDim.x + threadIdx.x;
    if (i < NN) {
        float4 v = d_agg2[i];
        float h3 = 0.f;
        float q;
        q = fmaxf(fmaf(v.x, d_s2[0], d_c2[0]), 0.f); h3 = fmaf(q, d_W3v[0], h3);
        q = fmaxf(fmaf(v.y, d_s2[1], d_c2[1]), 0.f); h3 = fmaf(q, d_W3v[1], h3);
        q = fmaxf(fmaf(v.z, d_s2[2], d_c2[2]), 0.f); h3 = fmaf(q, d_W3v[2], h3);
        q = fmaxf(fmaf(v.w, d_s2[3], d_c2[3]), 0.f); h3 = fmaf(q, d_W3v[3], h3);
        d_h3pre[i] = h3;
        float di = d_dinv[i];
        d_agg3[i] = h3 * di * di;
    }
}

// edge pass 3: scalar gather/scatter
__global__ void k_e3(const int* __restrict__ ei) {
    int e = blockIdx.x * blockDim.x + threadIdx.x;
    if (e < EE) {
        int s = ei[e];
        int d = ei[EE + e];
        atomicAdd(&d_agg3[d], d_norm[e] * d_h3pre[s]);
    }
}

// final: sigmoid(agg3*We + (b3*We+bee))
__global__ void k_out(float* __restrict__ out) {
    int i = blockIdx.x * blockDim.x + threadIdx.x;
    if (i < NN) {
        float z = fmaf(d_agg3[i], d_za, d_zc);
        out[i] = 1.0f / (1.0f + __expf(-z));
    }
}

// ---------------- launch ----------------
extern "C" void kernel_launch(void* const* d_in, const int* in_sizes, int n_in,
                              void* d_out, int out_size) {
    const float* x   = (const float*)d_in[0];
    const int*   ei  = (const int*)d_in[1];      // int32 [2, E] (JAX x64 disabled)
    const float* ew  = (const float*)d_in[2];
    const float* W1  = (const float*)d_in[3];
    const float* b1  = (const float*)d_in[4];
    const float* W2  = (const float*)d_in[5];
    const float* b2  = (const float*)d_in[6];
    const float* W3  = (const float*)d_in[7];
    const float* b3  = (const float*)d_in[8];
    const float* g1  = (const float*)d_in[9];
    const float* be1 = (const float*)d_in[10];
    const float* m1  = (const float*)d_in[11];
    const float* v1  = (const float*)d_in[12];
    const float* g2  = (const float*)d_in[13];
    const float* be2 = (const float*)d_in[14];
    const float* m2  = (const float*)d_in[15];
    const float* v2  = (const float*)d_in[16];
    const float* We  = (const float*)d_in[17];
    const float* bee = (const float*)d_in[18];

    const int TB = 256;
    const int NB_N = NN / TB;   // 1024
    const int NB_E = EE / TB;   // 16384

    k_params<<<1, 64>>>(W1, b1, W2, b2, W3, b3, g1, be1, m1, v1, g2, be2, m2, v2, We, bee);
    k_initdeg<<<NB_N, TB>>>();
    k_deg<<<NB_E, TB>>>(ei, ew);
    k_dinv<<<NB_N, TB>>>(x);
    k_e1<<<NB_E, TB>>>(ei, ew, x);
    k_n1<<<NB_N, TB>>>();
    k_e2<<<NB_E, TB>>>(ei);
    k_n2<<<NB_N, TB>>>();
    k_e3<<<NB_E, TB>>>(ei);
    k_out<<<NB_N, TB>>>((float*)d_out);
}

// round 4
// speedup vs baseline: 1.3235x; 1.3235x over previous
#include <cuda_runtime.h>

// Problem-fixed shapes
#define NN 262144
#define EE 4194304
#define BN_EPS 1e-5f

// ---------------- scratch (static device globals; no allocation) ----------------
__device__ float  d_deg[NN];
__device__ float  d_dinv[NN];
__device__ float  d_agg1[NN];
__device__ float  d_h3pre[NN];
__device__ float  d_agg3[NN];
__device__ float4 d_h2pre[NN];
__device__ float4 d_agg2[NN];
__device__ float  d_norm[EE];   // per-edge symmetric norm (shared by all 3 layers)

// folded per-layer affine params
__device__ float d_a1[16], d_c1[16];   // layer1: relu(agg1*a1 + c1)
__device__ float d_W2v[64];            // [16,4] row-major
__device__ float d_s2[4], d_c2[4];     // layer2 bn fold
__device__ float d_W3v[4];
__device__ float d_za, d_zc;           // final: sigmoid(agg3*za + zc)

// 16B vector reduction (sm_90+): one LTS op instead of four scalar REDs
__device__ __forceinline__ void red_add_v4(float4* addr, float a, float b, float c, float d) {
    asm volatile("red.global.add.v4.f32 [%0], {%1, %2, %3, %4};"
                 :: "l"(addr), "f"(a), "f"(b), "f"(c), "f"(d) : "memory");
}

// ---------------- kernels ----------------

// fused: init deg to self-loop weight 1.0; block 0 also folds the affine params
__global__ void k_init(const float* __restrict__ W1, const float* __restrict__ b1,
                       const float* __restrict__ W2, const float* __restrict__ b2,
                       const float* __restrict__ W3, const float* __restrict__ b3,
                       const float* __restrict__ g1, const float* __restrict__ be1,
                       const float* __restrict__ m1, const float* __restrict__ v1,
                       const float* __restrict__ g2, const float* __restrict__ be2,
                       const float* __restrict__ m2, const float* __restrict__ v2,
                       const float* __restrict__ We, const float* __restrict__ bee) {
    int i = blockIdx.x * blockDim.x + threadIdx.x;
    if (i < NN) d_deg[i] = 1.0f;
    if (blockIdx.x == 0) {
        int t = threadIdx.x;
        if (t < 16) {
            float s = g1[t] * rsqrtf(v1[t] + BN_EPS);
            d_a1[t] = W1[t] * s;
            d_c1[t] = (b1[t] - m1[t]) * s + be1[t];
        }
        if (t < 64) d_W2v[t] = W2[t];
        if (t < 4) {
            float s = g2[t] * rsqrtf(v2[t] + BN_EPS);
            d_s2[t] = s;
            d_c2[t] = (b2[t] - m2[t]) * s + be2[t];
            d_W3v[t] = W3[t];
        }
        if (t == 0) { d_za = We[0]; d_zc = b3[0] * We[0] + bee[0]; }
    }
}

// degree accumulation: 4 edges/thread, vectorized streams
__global__ void k_deg(const int* __restrict__ ei, const float* __restrict__ ew) {
    int t = blockIdx.x * blockDim.x + threadIdx.x;   // t < EE/4
    if (t < EE / 4) {
        int4   dd = ((const int4*)(ei + EE))[t];
        float4 w  = ((const float4*)ew)[t];
        atomicAdd(&d_deg[dd.x], w.x);
        atomicAdd(&d_deg[dd.y], w.y);
        atomicAdd(&d_deg[dd.z], w.z);
        atomicAdd(&d_deg[dd.w], w.w);
    }
}

// dinv + layer-1 self-loop init: agg1[i] = dinv^2 * x[i]
__global__ void k_dinv(const float* __restrict__ x) {
    int i = blockIdx.x * blockDim.x + threadIdx.x;
    if (i < NN) {
        float di = rsqrtf(d_deg[i]);
        d_dinv[i] = di;
        d_agg1[i] = x[i] * di * di;
    }
}

// edge pass 1: compute+store norm, scalar gather/scatter of x (4 edges/thread)
__global__ void k_e1(const int* __restrict__ ei, const float* __restrict__ ew,
                     const float* __restrict__ x) {
    int t = blockIdx.x * blockDim.x + threadIdx.x;
    if (t < EE / 4) {
        int4   ss = ((const int4*)ei)[t];
        int4   dd = ((const int4*)(ei + EE))[t];
        float4 w  = ((const float4*)ew)[t];
        float4 nm;
        nm.x = __ldg(&d_dinv[ss.x]) * w.x * __ldg(&d_dinv[dd.x]);
        nm.y = __ldg(&d_dinv[ss.y]) * w.y * __ldg(&d_dinv[dd.y]);
        nm.z = __ldg(&d_dinv[ss.z]) * w.z * __ldg(&d_dinv[dd.z]);
        nm.w = __ldg(&d_dinv[ss.w]) * w.w * __ldg(&d_dinv[dd.w]);
        ((float4*)d_norm)[t] = nm;
        atomicAdd(&d_agg1[dd.x], nm.x * __ldg(&x[ss.x]));
        atomicAdd(&d_agg1[dd.y], nm.y * __ldg(&x[ss.y]));
        atomicAdd(&d_agg1[dd.z], nm.z * __ldg(&x[ss.z]));
        atomicAdd(&d_agg1[dd.w], nm.w * __ldg(&x[ss.w]));
    }
}

// node pass 1: bias+bn+relu (folded) -> W2 -> h2pre; init agg2 with self loop
__global__ void k_n1() {
    int i = blockIdx.x * blockDim.x + threadIdx.x;
    if (i < NN) {
        float t = d_agg1[i];
        float a0 = 0.f, a1 = 0.f, a2 = 0.f, a3 = 0.f;
#pragma unroll
        for (int j = 0; j < 16; j++) {
            float p = fmaxf(fmaf(t, d_a1[j], d_c1[j]), 0.f);
            a0 = fmaf(p, d_W2v[j * 4 + 0], a0);
            a1 = fmaf(p, d_W2v[j * 4 + 1], a1);
            a2 = fmaf(p, d_W2v[j * 4 + 2], a2);
            a3 = fmaf(p, d_W2v[j * 4 + 3], a3);
        }
        float4 h = make_float4(a0, a1, a2, a3);
        d_h2pre[i] = h;
        float di = d_dinv[i];
        float r = di * di;
        d_agg2[i] = make_float4(h.x * r, h.y * r, h.z * r, h.w * r);
    }
}

// edge pass 2: 4-wide gather + vector reduction (4 edges/thread)
__global__ void k_e2(const int* __restrict__ ei) {
    int t = blockIdx.x * blockDim.x + threadIdx.x;
    if (t < EE / 4) {
        int4   ss = ((const int4*)ei)[t];
        int4   dd = ((const int4*)(ei + EE))[t];
        float4 nm = ((const float4*)d_norm)[t];
        float4 h;
        h = d_h2pre[ss.x]; red_add_v4(&d_agg2[dd.x], nm.x * h.x, nm.x * h.y, nm.x * h.z, nm.x * h.w);
        h = d_h2pre[ss.y]; red_add_v4(&d_agg2[dd.y], nm.y * h.x, nm.y * h.y, nm.y * h.z, nm.y * h.w);
        h = d_h2pre[ss.z]; red_add_v4(&d_agg2[dd.z], nm.z * h.x, nm.z * h.y, nm.z * h.z, nm.z * h.w);
        h = d_h2pre[ss.w]; red_add_v4(&d_agg2[dd.w], nm.w * h.x, nm.w * h.y, nm.w * h.z, nm.w * h.w);
    }
}

// node pass 2: bias+bn+relu (folded) -> W3 -> h3pre; init agg3 with self loop
__global__ void k_n2() {
    int i = blockIdx.x * blockDim.x + threadIdx.x;
    if (i < NN) {
        float4 v = d_agg2[i];
        float h3 = 0.f;
        float q;
        q = fmaxf(fmaf(v.x, d_s2[0], d_c2[0]), 0.f); h3 = fmaf(q, d_W3v[0], h3);
        q = fmaxf(fmaf(v.y, d_s2[1], d_c2[1]), 0.f); h3 = fmaf(q, d_W3v[1], h3);
        q = fmaxf(fmaf(v.z, d_s2[2], d_c2[2]), 0.f); h3 = fmaf(q, d_W3v[2], h3);
        q = fmaxf(fmaf(v.w, d_s2[3], d_c2[3]), 0.f); h3 = fmaf(q, d_W3v[3], h3);
        d_h3pre[i] = h3;
        float di = d_dinv[i];
        d_agg3[i] = h3 * di * di;
    }
}

// edge pass 3: scalar gather/scatter (4 edges/thread)
__global__ void k_e3(const int* __restrict__ ei) {
    int t = blockIdx.x * blockDim.x + threadIdx.x;
    if (t < EE / 4) {
        int4   ss = ((const int4*)ei)[t];
        int4   dd = ((const int4*)(ei + EE))[t];
        float4 nm = ((const float4*)d_norm)[t];
        atomicAdd(&d_agg3[dd.x], nm.x * __ldg(&d_h3pre[ss.x]));
        atomicAdd(&d_agg3[dd.y], nm.y * __ldg(&d_h3pre[ss.y]));
        atomicAdd(&d_agg3[dd.z], nm.z * __ldg(&d_h3pre[ss.z]));
        atomicAdd(&d_agg3[dd.w], nm.w * __ldg(&d_h3pre[ss.w]));
    }
}

// final: sigmoid(agg3*We + (b3*We+bee))
__global__ void k_out(float* __restrict__ out) {
    int i = blockIdx.x * blockDim.x + threadIdx.x;
    if (i < NN) {
        float z = fmaf(d_agg3[i], d_za, d_zc);
        out[i] = 1.0f / (1.0f + __expf(-z));
    }
}

// ---------------- launch ----------------
extern "C" void kernel_launch(void* const* d_in, const int* in_sizes, int n_in,
                              void* d_out, int out_size) {
    const float* x   = (const float*)d_in[0];
    const int*   ei  = (const int*)d_in[1];      // int32 [2, E]
    const float* ew  = (const float*)d_in[2];
    const float* W1  = (const float*)d_in[3];
    const float* b1  = (const float*)d_in[4];
    const float* W2  = (const float*)d_in[5];
    const float* b2  = (const float*)d_in[6];
    const float* W3  = (const float*)d_in[7];
    const float* b3  = (const float*)d_in[8];
    const float* g1  = (const float*)d_in[9];
    const float* be1 = (const float*)d_in[10];
    const float* m1  = (const float*)d_in[11];
    const float* v1  = (const float*)d_in[12];
    const float* g2  = (const float*)d_in[13];
    const float* be2 = (const float*)d_in[14];
    const float* m2  = (const float*)d_in[15];
    const float* v2  = (const float*)d_in[16];
    const float* We  = (const float*)d_in[17];
    const float* bee = (const float*)d_in[18];

    const int TB = 256;
    const int NB_N  = NN / TB;        // 1024
    const int NB_E4 = EE / 4 / TB;    // 4096

    k_init<<<NB_N, TB>>>(W1, b1, W2, b2, W3, b3, g1, be1, m1, v1, g2, be2, m2, v2, We, bee);
    k_deg<<<NB_E4, TB>>>(ei, ew);
    k_dinv<<<NB_N, TB>>>(x);
    k_e1<<<NB_E4, TB>>>(ei, ew, x);
    k_n1<<<NB_N, TB>>>();
    k_e2<<<NB_E4, TB>>>(ei);
    k_n2<<<NB_N, TB>>>();
    k_e3<<<NB_E4, TB>>>(ei);
    k_out<<<NB_N, TB>>>((float*)d_out);
}

// round 5
// speedup vs baseline: 1.5208x; 1.1490x over previous
#include <cuda_runtime.h>

// Problem-fixed shapes
#define NN 262144
#define EE 4194304
#define BN_EPS 1e-5f

// ---------------- scratch (static device globals; no allocation) ----------------
__device__ float  d_deg[NN];
__device__ float  d_dinv[NN];
__device__ float  d_gx[NN];     // dinv[i] * x[i]
__device__ float  d_agg1[NN];   // init gx[i], accum S1
__device__ float4 d_g2[NN];     // dinv[i] * h2pre[i]
__device__ float4 d_agg2[NN];   // init g2[i], accum S2
__device__ float  d_g3[NN];     // dinv[i] * h3pre[i]
__device__ float  d_agg3[NN];   // init g3[i], accum S3

// folded per-layer affine params
__device__ float d_a1[16], d_c1[16];   // layer1: relu(t*a1 + c1)
__device__ float d_W2v[64];            // [16,4] row-major
__device__ float d_s2[4], d_c2[4];     // layer2 bn fold
__device__ float d_W3v[4];
__device__ float d_za, d_zc;           // final: sigmoid(agg3*dinv*za + zc)

// 16B vector reduction (sm_90+): one LTS op instead of four scalar REDs
__device__ __forceinline__ void red_add_v4(float4* addr, float a, float b, float c, float d) {
    asm volatile("red.global.add.v4.f32 [%0], {%1, %2, %3, %4};"
                 :: "l"(addr), "f"(a), "f"(b), "f"(c), "f"(d) : "memory");
}

// ---------------- kernels ----------------

// fused: init deg to self-loop weight 1.0; block 0 also folds the affine params
__global__ void k_init(const float* __restrict__ W1, const float* __restrict__ b1,
                       const float* __restrict__ W2, const float* __restrict__ b2,
                       const float* __restrict__ W3, const float* __restrict__ b3,
                       const float* __restrict__ g1, const float* __restrict__ be1,
                       const float* __restrict__ m1, const float* __restrict__ v1,
                       const float* __restrict__ g2, const float* __restrict__ be2,
                       const float* __restrict__ m2, const float* __restrict__ v2,
                       const float* __restrict__ We, const float* __restrict__ bee) {
    int i = blockIdx.x * blockDim.x + threadIdx.x;
    if (i < NN) d_deg[i] = 1.0f;
    if (blockIdx.x == 0) {
        int t = threadIdx.x;
        if (t < 16) {
            float s = g1[t] * rsqrtf(v1[t] + BN_EPS);
            d_a1[t] = W1[t] * s;
            d_c1[t] = (b1[t] - m1[t]) * s + be1[t];
        }
        if (t < 64) d_W2v[t] = W2[t];
        if (t < 4) {
            float s = g2[t] * rsqrtf(v2[t] + BN_EPS);
            d_s2[t] = s;
            d_c2[t] = (b2[t] - m2[t]) * s + be2[t];
            d_W3v[t] = W3[t];
        }
        if (t == 0) { d_za = We[0]; d_zc = b3[0] * We[0] + bee[0]; }
    }
}

// degree accumulation: 8 edges/thread, vectorized streams
__global__ void k_deg(const int* __restrict__ ei, const float* __restrict__ ew) {
    int t = blockIdx.x * blockDim.x + threadIdx.x;   // t < EE/8
    if (t < EE / 8) {
#pragma unroll
        for (int r = 0; r < 2; r++) {
            int4   dd = ((const int4*)(ei + EE))[2 * t + r];
            float4 w  = ((const float4*)ew)[2 * t + r];
            atomicAdd(&d_deg[dd.x], w.x);
            atomicAdd(&d_deg[dd.y], w.y);
            atomicAdd(&d_deg[dd.z], w.z);
            atomicAdd(&d_deg[dd.w], w.w);
        }
    }
}

// dinv, gx = dinv*x, agg1 init = gx (self-loop term folded: out = dinv*(S + gx))
__global__ void k_dinv(const float* __restrict__ x) {
    int i = blockIdx.x * blockDim.x + threadIdx.x;
    if (i < NN) {
        float di = rsqrtf(d_deg[i]);
        d_dinv[i] = di;
        float g = x[i] * di;
        d_gx[i] = g;
        d_agg1[i] = g;
    }
}

// edge pass 1: agg1[d] += w * gx[s]  (ONE divergent gather + one atomic per edge)
__global__ void k_e1(const int* __restrict__ ei, const float* __restrict__ ew) {
    int t = blockIdx.x * blockDim.x + threadIdx.x;   // t < EE/8
    if (t < EE / 8) {
#pragma unroll
        for (int r = 0; r < 2; r++) {
            int4   ss = ((const int4*)ei)[2 * t + r];
            int4   dd = ((const int4*)(ei + EE))[2 * t + r];
            float4 w  = ((const float4*)ew)[2 * t + r];
            atomicAdd(&d_agg1[dd.x], w.x * __ldg(&d_gx[ss.x]));
            atomicAdd(&d_agg1[dd.y], w.y * __ldg(&d_gx[ss.y]));
            atomicAdd(&d_agg1[dd.z], w.z * __ldg(&d_gx[ss.z]));
            atomicAdd(&d_agg1[dd.w], w.w * __ldg(&d_gx[ss.w]));
        }
    }
}

// node pass 1: t = dinv*(agg1); folded bn+relu -> W2 -> h2; g2 = dinv*h2; agg2 init = g2
__global__ void k_n1() {
    int i = blockIdx.x * blockDim.x + threadIdx.x;
    if (i < NN) {
        float di = d_dinv[i];
        float t = di * d_agg1[i];
        float a0 = 0.f, a1 = 0.f, a2 = 0.f, a3 = 0.f;
#pragma unroll
        for (int j = 0; j < 16; j++) {
            float p = fmaxf(fmaf(t, d_a1[j], d_c1[j]), 0.f);
            a0 = fmaf(p, d_W2v[j * 4 + 0], a0);
            a1 = fmaf(p, d_W2v[j * 4 + 1], a1);
            a2 = fmaf(p, d_W2v[j * 4 + 2], a2);
            a3 = fmaf(p, d_W2v[j * 4 + 3], a3);
        }
        float4 g = make_float4(a0 * di, a1 * di, a2 * di, a3 * di);
        d_g2[i] = g;
        d_agg2[i] = g;
    }
}

// edge pass 2: agg2[d] += w * g2[s]  (16B gather + 16B vector reduction)
__global__ void k_e2(const int* __restrict__ ei, const float* __restrict__ ew) {
    int t = blockIdx.x * blockDim.x + threadIdx.x;   // t < EE/4
    if (t < EE / 4) {
        int4   ss = ((const int4*)ei)[t];
        int4   dd = ((const int4*)(ei + EE))[t];
        float4 w  = ((const float4*)ew)[t];
        float4 h;
        h = d_g2[ss.x]; red_add_v4(&d_agg2[dd.x], w.x * h.x, w.x * h.y, w.x * h.z, w.x * h.w);
        h = d_g2[ss.y]; red_add_v4(&d_agg2[dd.y], w.y * h.x, w.y * h.y, w.y * h.z, w.y * h.w);
        h = d_g2[ss.z]; red_add_v4(&d_agg2[dd.z], w.z * h.x, w.z * h.y, w.z * h.z, w.z * h.w);
        h = d_g2[ss.w]; red_add_v4(&d_agg2[dd.w], w.w * h.x, w.w * h.y, w.w * h.z, w.w * h.w);
    }
}

// node pass 2: v = dinv*agg2; folded bn+relu -> W3 -> h3; g3 = dinv*h3; agg3 init = g3
__global__ void k_n2() {
    int i = blockIdx.x * blockDim.x + threadIdx.x;
    if (i < NN) {
        float di = d_dinv[i];
        float4 v = d_agg2[i];
        float h3 = 0.f;
        float q;
        q = fmaxf(fmaf(di * v.x, d_s2[0], d_c2[0]), 0.f); h3 = fmaf(q, d_W3v[0], h3);
        q = fmaxf(fmaf(di * v.y, d_s2[1], d_c2[1]), 0.f); h3 = fmaf(q, d_W3v[1], h3);
        q = fmaxf(fmaf(di * v.z, d_s2[2], d_c2[2]), 0.f); h3 = fmaf(q, d_W3v[2], h3);
        q = fmaxf(fmaf(di * v.w, d_s2[3], d_c2[3]), 0.f); h3 = fmaf(q, d_W3v[3], h3);
        float g = h3 * di;
        d_g3[i] = g;
        d_agg3[i] = g;
    }
}

// edge pass 3: agg3[d] += w * g3[s]
__global__ void k_e3(const int* __restrict__ ei, const float* __restrict__ ew) {
    int t = blockIdx.x * blockDim.x + threadIdx.x;   // t < EE/8
    if (t < EE / 8) {
#pragma unroll
        for (int r = 0; r < 2; r++) {
            int4   ss = ((const int4*)ei)[2 * t + r];
            int4   dd = ((const int4*)(ei + EE))[2 * t + r];
            float4 w  = ((const float4*)ew)[2 * t + r];
            atomicAdd(&d_agg3[dd.x], w.x * __ldg(&d_g3[ss.x]));
            atomicAdd(&d_agg3[dd.y], w.y * __ldg(&d_g3[ss.y]));
            atomicAdd(&d_agg3[dd.z], w.z * __ldg(&d_g3[ss.z]));
            atomicAdd(&d_agg3[dd.w], w.w * __ldg(&d_g3[ss.w]));
        }
    }
}

// final: sigmoid(dinv*agg3*za + zc)
__global__ void k_out(float* __restrict__ out) {
    int i = blockIdx.x * blockDim.x + threadIdx.x;
    if (i < NN) {
        float z = fmaf(d_dinv[i] * d_agg3[i], d_za, d_zc);
        out[i] = 1.0f / (1.0f + __expf(-z));
    }
}

// ---------------- launch ----------------
extern "C" void kernel_launch(void* const* d_in, const int* in_sizes, int n_in,
                              void* d_out, int out_size) {
    const float* x   = (const float*)d_in[0];
    const int*   ei  = (const int*)d_in[1];      // int32 [2, E]
    const float* ew  = (const float*)d_in[2];
    const float* W1  = (const float*)d_in[3];
    const float* b1  = (const float*)d_in[4];
    const float* W2  = (const float*)d_in[5];
    const float* b2  = (const float*)d_in[6];
    const float* W3  = (const float*)d_in[7];
    const float* b3  = (const float*)d_in[8];
    const float* g1  = (const float*)d_in[9];
    const float* be1 = (const float*)d_in[10];
    const float* m1  = (const float*)d_in[11];
    const float* v1  = (const float*)d_in[12];
    const float* g2  = (const float*)d_in[13];
    const float* be2 = (const float*)d_in[14];
    const float* m2  = (const float*)d_in[15];
    const float* v2  = (const float*)d_in[16];
    const float* We  = (const float*)d_in[17];
    const float* bee = (const float*)d_in[18];

    const int TB = 256;
    const int NB_N  = NN / TB;        // 1024
    const int NB_E4 = EE / 4 / TB;    // 4096
    const int NB_E8 = EE / 8 / TB;    // 2048

    k_init<<<NB_N, TB>>>(W1, b1, W2, b2, W3, b3, g1, be1, m1, v1, g2, be2, m2, v2, We, bee);
    k_deg<<<NB_E8, TB>>>(ei, ew);
    k_dinv<<<NB_N, TB>>>(x);
    k_e1<<<NB_E8, TB>>>(ei, ew);
    k_n1<<<NB_N, TB>>>();
    k_e2<<<NB_E4, TB>>>(ei, ew);
    k_n2<<<NB_N, TB>>>();
    k_e3<<<NB_E8, TB>>>(ei, ew);
    k_out<<<NB_N, TB>>>((float*)d_out);
}

// round 7
// speedup vs baseline: 1.5231x; 1.0016x over previous
#include <cuda_runtime.h>
#include <cuda_fp16.h>

// Problem-fixed shapes
#define NN 262144
#define EE 4194304
#define BN_EPS 1e-5f

// ---------------- scratch (static device globals; no allocation) ----------------
__device__ float  d_deg[NN];
__device__ float  d_dinv[NN];
__device__ __half d_gx[NN];       // f16: dinv[i] * x[i]          (512 KB)
__device__ float  d_agg1[NN];     // f32 accumulators
__device__ __half d_g2[NN * 4];   // f16 half4 per node           (2 MB)
__device__ float4 d_agg2[NN];
__device__ __half d_g3[NN];       // f16                          (512 KB)
__device__ float  d_agg3[NN];

// folded per-layer affine params
__device__ float d_a1[16], d_c1[16];   // layer1: relu(t*a1 + c1)
__device__ float d_W2v[64];            // [16,4] row-major
__device__ float d_s2[4], d_c2[4];     // layer2 bn fold
__device__ float d_W3v[4];
__device__ float d_za, d_zc;           // final: sigmoid(agg3*dinv*za + zc)

// 16B vector reduction (sm_90+): one LTS op instead of four scalar REDs
__device__ __forceinline__ void red_add_v4(float4* addr, float a, float b, float c, float d) {
    asm volatile("red.global.add.v4.f32 [%0], {%1, %2, %3, %4};"
                 :: "l"(addr), "f"(a), "f"(b), "f"(c), "f"(d) : "memory");
}

// ---------------- kernels ----------------

// fused: init deg to self-loop weight 1.0; block 0 also folds the affine params
__global__ void k_init(const float* __restrict__ W1, const float* __restrict__ b1,
                       const float* __restrict__ W2, const float* __restrict__ b2,
                       const float* __restrict__ W3, const float* __restrict__ b3,
                       const float* __restrict__ g1, const float* __restrict__ be1,
                       const float* __restrict__ m1, const float* __restrict__ v1,
                       const float* __restrict__ g2, const float* __restrict__ be2,
                       const float* __restrict__ m2, const float* __restrict__ v2,
                       const float* __restrict__ We, const float* __restrict__ bee) {
    int i = blockIdx.x * blockDim.x + threadIdx.x;
    if (i < NN) d_deg[i] = 1.0f;
    if (blockIdx.x == 0) {
        int t = threadIdx.x;
        if (t < 16) {
            float s = g1[t] * rsqrtf(v1[t] + BN_EPS);
            d_a1[t] = W1[t] * s;
            d_c1[t] = (b1[t] - m1[t]) * s + be1[t];
        }
        if (t < 64) d_W2v[t] = W2[t];
        if (t < 4) {
            float s = g2[t] * rsqrtf(v2[t] + BN_EPS);
            d_s2[t] = s;
            d_c2[t] = (b2[t] - m2[t]) * s + be2[t];
            d_W3v[t] = W3[t];
        }
        if (t == 0) { d_za = We[0]; d_zc = b3[0] * We[0] + bee[0]; }
    }
}

// degree accumulation: 8 edges/thread, vectorized streams
__global__ void k_deg(const int* __restrict__ ei, const float* __restrict__ ew) {
    int t = blockIdx.x * blockDim.x + threadIdx.x;   // t < EE/8
    if (t < EE / 8) {
#pragma unroll
        for (int r = 0; r < 2; r++) {
            int4   dd = ((const int4*)(ei + EE))[2 * t + r];
            float4 w  = ((const float4*)ew)[2 * t + r];
            atomicAdd(&d_deg[dd.x], w.x);
            atomicAdd(&d_deg[dd.y], w.y);
            atomicAdd(&d_deg[dd.z], w.z);
            atomicAdd(&d_deg[dd.w], w.w);
        }
    }
}

// dinv, gx = dinv*x (f16), agg1 init = gx (f32)
__global__ void k_dinv(const float* __restrict__ x) {
    int i = blockIdx.x * blockDim.x + threadIdx.x;
    if (i < NN) {
        float di = rsqrtf(d_deg[i]);
        d_dinv[i] = di;
        float g = x[i] * di;
        d_gx[i] = __float2half(g);
        d_agg1[i] = g;
    }
}

// edge pass 1: agg1[d] += w * gx[s]  (one 2B gather + one f32 atomic per edge)
__global__ void k_e1(const int* __restrict__ ei, const float* __restrict__ ew) {
    int t = blockIdx.x * blockDim.x + threadIdx.x;   // t < EE/8
    if (t < EE / 8) {
#pragma unroll
        for (int r = 0; r < 2; r++) {
            int4   ss = ((const int4*)ei)[2 * t + r];
            int4   dd = ((const int4*)(ei + EE))[2 * t + r];
            float4 w  = ((const float4*)ew)[2 * t + r];
            atomicAdd(&d_agg1[dd.x], w.x * __half2float(__ldg(&d_gx[ss.x])));
            atomicAdd(&d_agg1[dd.y], w.y * __half2float(__ldg(&d_gx[ss.y])));
            atomicAdd(&d_agg1[dd.z], w.z * __half2float(__ldg(&d_gx[ss.z])));
            atomicAdd(&d_agg1[dd.w], w.w * __half2float(__ldg(&d_gx[ss.w])));
        }
    }
}

// node pass 1: t = dinv*agg1; folded bn+relu -> W2 -> h2; g2 = dinv*h2 (half4); agg2 init
__global__ void k_n1() {
    int i = blockIdx.x * blockDim.x + threadIdx.x;
    if (i < NN) {
        float di = d_dinv[i];
        float t = di * d_agg1[i];
        float a0 = 0.f, a1 = 0.f, a2 = 0.f, a3 = 0.f;
#pragma unroll
        for (int j = 0; j < 16; j++) {
            float p = fmaxf(fmaf(t, d_a1[j], d_c1[j]), 0.f);
            a0 = fmaf(p, d_W2v[j * 4 + 0], a0);
            a1 = fmaf(p, d_W2v[j * 4 + 1], a1);
            a2 = fmaf(p, d_W2v[j * 4 + 2], a2);
            a3 = fmaf(p, d_W2v[j * 4 + 3], a3);
        }
        float4 g = make_float4(a0 * di, a1 * di, a2 * di, a3 * di);
        __half2 h01 = __floats2half2_rn(g.x, g.y);
        __half2 h23 = __floats2half2_rn(g.z, g.w);
        uint2 pk;
        pk.x = *(unsigned int*)&h01;
        pk.y = *(unsigned int*)&h23;
        ((uint2*)d_g2)[i] = pk;
        d_agg2[i] = g;
    }
}

__device__ __forceinline__ float4 ldg_half4(int idx) {
    uint2 pk = __ldg(&((const uint2*)d_g2)[idx]);
    __half2 h01 = *(__half2*)&pk.x;
    __half2 h23 = *(__half2*)&pk.y;
    float2 f01 = __half22float2(h01);
    float2 f23 = __half22float2(h23);
    return make_float4(f01.x, f01.y, f23.x, f23.y);
}

// edge pass 2: agg2[d] += w * g2[s]  (8B gather + 16B vector reduction; 8 edges/thread)
__global__ void k_e2(const int* __restrict__ ei, const float* __restrict__ ew) {
    int t = blockIdx.x * blockDim.x + threadIdx.x;   // t < EE/8
    if (t < EE / 8) {
#pragma unroll
        for (int r = 0; r < 2; r++) {
            int4   ss = ((const int4*)ei)[2 * t + r];
            int4   dd = ((const int4*)(ei + EE))[2 * t + r];
            float4 w  = ((const float4*)ew)[2 * t + r];
            float4 h;
            h = ldg_half4(ss.x); red_add_v4(&d_agg2[dd.x], w.x * h.x, w.x * h.y, w.x * h.z, w.x * h.w);
            h = ldg_half4(ss.y); red_add_v4(&d_agg2[dd.y], w.y * h.x, w.y * h.y, w.y * h.z, w.y * h.w);
            h = ldg_half4(ss.z); red_add_v4(&d_agg2[dd.z], w.z * h.x, w.z * h.y, w.z * h.z, w.z * h.w);
            h = ldg_half4(ss.w); red_add_v4(&d_agg2[dd.w], w.w * h.x, w.w * h.y, w.w * h.z, w.w * h.w);
        }
    }
}

// node pass 2: v = dinv*agg2; folded bn+relu -> W3 -> h3; g3 = dinv*h3 (f16); agg3 init
__global__ void k_n2() {
    int i = blockIdx.x * blockDim.x + threadIdx.x;
    if (i < NN) {
        float di = d_dinv[i];
        float4 v = d_agg2[i];
        float h3 = 0.f;
        float q;
        q = fmaxf(fmaf(di * v.x, d_s2[0], d_c2[0]), 0.f); h3 = fmaf(q, d_W3v[0], h3);
        q = fmaxf(fmaf(di * v.y, d_s2[1], d_c2[1]), 0.f); h3 = fmaf(q, d_W3v[1], h3);
        q = fmaxf(fmaf(di * v.z, d_s2[2], d_c2[2]), 0.f); h3 = fmaf(q, d_W3v[2], h3);
        q = fmaxf(fmaf(di * v.w, d_s2[3], d_c2[3]), 0.f); h3 = fmaf(q, d_W3v[3], h3);
        float g = h3 * di;
        d_g3[i] = __float2half(g);
        d_agg3[i] = g;
    }
}

// edge pass 3: agg3[d] += w * g3[s]
__global__ void k_e3(const int* __restrict__ ei, const float* __restrict__ ew) {
    int t = blockIdx.x * blockDim.x + threadIdx.x;   // t < EE/8
    if (t < EE / 8) {
#pragma unroll
        for (int r = 0; r < 2; r++) {
            int4   ss = ((const int4*)ei)[2 * t + r];
            int4   dd = ((const int4*)(ei + EE))[2 * t + r];
            float4 w  = ((const float4*)ew)[2 * t + r];
            atomicAdd(&d_agg3[dd.x], w.x * __half2float(__ldg(&d_g3[ss.x])));
            atomicAdd(&d_agg3[dd.y], w.y * __half2float(__ldg(&d_g3[ss.y])));
            atomicAdd(&d_agg3[dd.z], w.z * __half2float(__ldg(&d_g3[ss.z])));
            atomicAdd(&d_agg3[dd.w], w.w * __half2float(__ldg(&d_g3[ss.w])));
        }
    }
}

// final: sigmoid(dinv*agg3*za + zc)
__global__ void k_out(float* __restrict__ out) {
    int i = blockIdx.x * blockDim.x + threadIdx.x;
    if (i < NN) {
        float z = fmaf(d_dinv[i] * d_agg3[i], d_za, d_zc);
        out[i] = 1.0f / (1.0f + __expf(-z));
    }
}

// ---------------- launch ----------------
extern "C" void kernel_launch(void* const* d_in, const int* in_sizes, int n_in,
                              void* d_out, int out_size) {
    const float* x   = (const float*)d_in[0];
    const int*   ei  = (const int*)d_in[1];      // int32 [2, E]
    const float* ew  = (const float*)d_in[2];
    const float* W1  = (const float*)d_in[3];
    const float* b1  = (const float*)d_in[4];
    const float* W2  = (const float*)d_in[5];
    const float* b2  = (const float*)d_in[6];
    const float* W3  = (const float*)d_in[7];
    const float* b3  = (const float*)d_in[8];
    const float* g1  = (const float*)d_in[9];
    const float* be1 = (const float*)d_in[10];
    const float* m1  = (const float*)d_in[11];
    const float* v1  = (const float*)d_in[12];
    const float* g2  = (const float*)d_in[13];
    const float* be2 = (const float*)d_in[14];
    const float* m2  = (const float*)d_in[15];
    const float* v2  = (const float*)d_in[16];
    const float* We  = (const float*)d_in[17];
    const float* bee = (const float*)d_in[18];

    const int TB = 256;
    const int NB_N  = NN / TB;        // 1024
    const int NB_E8 = EE / 8 / TB;    // 2048

    k_init<<<NB_N, TB>>>(W1, b1, W2, b2, W3, b3, g1, be1, m1, v1, g2, be2, m2, v2, We, bee);
    k_deg<<<NB_E8, TB>>>(ei, ew);
    k_dinv<<<NB_N, TB>>>(x);
    k_e1<<<NB_E8, TB>>>(ei, ew);
    k_n1<<<NB_N, TB>>>();
    k_e2<<<NB_E8, TB>>>(ei, ew);
    k_n2<<<NB_N, TB>>>();
    k_e3<<<NB_E8, TB>>>(ei, ew);
    k_out<<<NB_N, TB>>>((float*)d_out);
}